// round 17
// baseline (speedup 1.0000x reference)
#include <cuda_runtime.h>
#include <cuda_fp16.h>
#include <cstdint>

#define NN 100000
#define NN_PAD 100096          // 782 * 128
#define NE 1600000
#define SCAN_NB 98             // ceil(NN/1024)

// ---------------- scratch (static __device__ arrays; no allocation) ----------
// g_scan_cnt must be ZERO at entry: module load zero-inits it and the scan1
// finalize block resets it every invocation (deterministic across replays).
__device__ __half g_yh[NN_PAD * 256]; // [N,256] fp16, k-PERMUTED layout (see spmm)
__device__ uint2  g_f0[NN * 32];      // [N,128] fp16 features buffer A
__device__ uint2  g_f1[NN * 32];      // [N,128] fp16 features buffer B
__device__ int2   g_csr2[NE];         // {src id, ns_bits} grouped by dst
__device__ int    g_rank[NE];         // per-edge rank within its dst bucket
__device__ int    g_outdeg[NN];
__device__ int    g_indeg[NN];
__device__ float  g_ns[NN];
__device__ float  g_nd[NN];
__device__ int    g_rowstart[NN];     // block-LOCAL exclusive scan of indeg
__device__ int    g_blocksums[128];
__device__ int    g_pre[128];         // global exclusive block offsets
__device__ int    g_scan_cnt;
__device__ __half g_wt0[128 * 256];   // [128n][256k'] fp16, k-permuted [w0;rw0]
__device__ __half g_wt1[128 * 256];   // [128n][256k'] fp16, k-permuted [w1;rw1]
__device__ __half g_wt2[64 * 256];    // [64n][256k']  fp16, k-permuted [w2;rw2]

// k-permutation: k' = lane*8 + c ; c<4 -> weighted channel lane*4+c,
//                c>=4 -> raw channel lane*4+(c-4). Applied to A rows (spmm
// stores) and weight rows identically, so the GEMM dot product is unchanged.

// ---------------- helpers ----------------------------------------------------
__device__ __forceinline__ void mma_f16(float* c, const uint32_t* a, const uint32_t* b) {
    asm volatile(
        "mma.sync.aligned.m16n8k16.row.col.f32.f16.f16.f32 "
        "{%0,%1,%2,%3}, {%4,%5,%6,%7}, {%8,%9}, {%0,%1,%2,%3};\n"
        : "+f"(c[0]), "+f"(c[1]), "+f"(c[2]), "+f"(c[3])
        : "r"(a[0]), "r"(a[1]), "r"(a[2]), "r"(a[3]), "r"(b[0]), "r"(b[1]));
}

__device__ __forceinline__ void ldsm_x4(uint32_t* r, uint32_t addr) {
    asm volatile(
        "ldmatrix.sync.aligned.m8n8.x4.shared.b16 {%0,%1,%2,%3}, [%4];"
        : "=r"(r[0]), "=r"(r[1]), "=r"(r[2]), "=r"(r[3]) : "r"(addr));
}

__device__ __forceinline__ void cp16(uint32_t dst, const void* src) {
    asm volatile("cp.async.cg.shared.global [%0], [%1], 16;\n" :: "r"(dst), "l"(src));
}
__device__ __forceinline__ void cpcommit() {
    asm volatile("cp.async.commit_group;\n");
}
template <int N>
__device__ __forceinline__ void cpwait() {
    asm volatile("cp.async.wait_group %0;\n" :: "n"(N));
}

// ---------------- fused prep: weights->fp16 permuted-T, zero degs, x->fp16 ----
__global__ void k_prep(const float4* __restrict__ raw_x,
                       const float* __restrict__ w0, const float* __restrict__ rw0,
                       const float* __restrict__ w1, const float* __restrict__ rw1,
                       const float* __restrict__ w2, const float* __restrict__ rw2) {
    int i = blockIdx.x * blockDim.x + threadIdx.x;
    if (i < 32768) {
        int kp = i >> 7, n = i & 127;
        int l = kp >> 3, c = kp & 7;
        int ch = l * 4 + (c & 3);
        float v = (c < 4) ? w0[ch * 128 + n] : rw0[ch * 128 + n];
        g_wt0[n * 256 + kp] = __float2half(v);
    } else if (i < 65536) {
        int j = i - 32768;
        int kp = j >> 7, n = j & 127;
        int l = kp >> 3, c = kp & 7;
        int ch = l * 4 + (c & 3);
        float v = (c < 4) ? w1[ch * 128 + n] : rw1[ch * 128 + n];
        g_wt1[n * 256 + kp] = __float2half(v);
    } else if (i < 81920) {
        int j = i - 65536;
        int kp = j >> 6, n = j & 63;
        int l = kp >> 3, c = kp & 7;
        int ch = l * 4 + (c & 3);
        float v = (c < 4) ? w2[ch * 64 + n] : rw2[ch * 64 + n];
        g_wt2[n * 256 + kp] = __float2half(v);
    } else if (i < 106920) {
        ((int4*)g_outdeg)[i - 81920] = make_int4(0, 0, 0, 0);
    } else if (i < 131920) {
        ((int4*)g_indeg)[i - 106920] = make_int4(0, 0, 0, 0);
    } else if (i < 3331920) {
        int j = i - 131920;                 // float4 index == uint2 index
        float4 v = raw_x[j];
        __half2 h0 = __floats2half2_rn(v.x, v.y);
        __half2 h1 = __floats2half2_rn(v.z, v.w);
        uint2 u;
        u.x = *reinterpret_cast<uint32_t*>(&h0);
        u.y = *reinterpret_cast<uint32_t*>(&h1);
        g_f0[j] = u;
    }
}

// ---------------- degree count + per-edge dst rank ----------------------------
__global__ void k_deg(const int4* __restrict__ src4, const int4* __restrict__ dst4) {
    int e = blockIdx.x * blockDim.x + threadIdx.x;
    if (e < NE / 4) {
        int4 s = src4[e];
        int4 d = dst4[e];
        atomicAdd(&g_outdeg[s.x], 1); atomicAdd(&g_outdeg[s.y], 1);
        atomicAdd(&g_outdeg[s.z], 1); atomicAdd(&g_outdeg[s.w], 1);
        int4 r;
        r.x = atomicAdd(&g_indeg[d.x], 1);
        r.y = atomicAdd(&g_indeg[d.y], 1);
        r.z = atomicAdd(&g_indeg[d.z], 1);
        r.w = atomicAdd(&g_indeg[d.w], 1);
        ((int4*)g_rank)[e] = r;
    }
}

// block-local scan + blocksums + norms + LAST-BLOCK finalize of g_pre ----------
__global__ void k_scan1() {
    __shared__ int sh[1024];
    __shared__ int last;
    int t = threadIdx.x;
    int i = blockIdx.x * 1024 + t;
    int v = (i < NN) ? g_indeg[i] : 0;
    sh[t] = v;
    if (t == 0) last = 0;
    __syncthreads();
    #pragma unroll
    for (int off = 1; off < 1024; off <<= 1) {
        int add = (t >= off) ? sh[t - off] : 0;
        __syncthreads();
        sh[t] += add;
        __syncthreads();
    }
    if (i < NN) {
        g_rowstart[i] = sh[t] - v;  // exclusive within block
        g_ns[i] = rsqrtf(fmaxf((float)g_outdeg[i], 1.0f));
        g_nd[i] = rsqrtf(fmaxf((float)v, 1.0f));
    }
    if (t == 1023) {
        g_blocksums[blockIdx.x] = sh[1023];
        __threadfence();
        int old = atomicAdd(&g_scan_cnt, 1);
        if (old == SCAN_NB - 1) last = 1;
    }
    __syncthreads();
    if (last) {
        __threadfence();
        int b = (t < SCAN_NB) ? *((volatile int*)&g_blocksums[t]) : 0;
        if (t < 128) sh[t] = b;
        __syncthreads();
        #pragma unroll
        for (int off = 1; off < 128; off <<= 1) {
            int add = (t < 128 && t >= off) ? sh[t - off] : 0;
            __syncthreads();
            if (t < 128) sh[t] += add;
            __syncthreads();
        }
        if (t < 128) g_pre[t] = (t < SCAN_NB) ? (sh[t] - b) : NE;  // exclusive
        if (t == 0) g_scan_cnt = 0;   // self-reset for next invocation
    }
}

// atomic-free CSR fill: pos = rowstart[dst] + g_pre[dst>>10] + rank -------------
__global__ void k_csr(const int4* __restrict__ src4, const int4* __restrict__ dst4) {
    int e = blockIdx.x * blockDim.x + threadIdx.x;
    if (e < NE / 4) {
        int4 s = src4[e];
        int4 d = dst4[e];
        int4 r = ((const int4*)g_rank)[e];
        int2 v;
        v.x = s.x; v.y = __float_as_int(g_ns[s.x]);
        g_csr2[g_rowstart[d.x] + g_pre[d.x >> 10] + r.x] = v;
        v.x = s.y; v.y = __float_as_int(g_ns[s.y]);
        g_csr2[g_rowstart[d.y] + g_pre[d.y >> 10] + r.y] = v;
        v.x = s.z; v.y = __float_as_int(g_ns[s.z]);
        g_csr2[g_rowstart[d.z] + g_pre[d.z >> 10] + r.z] = v;
        v.x = s.w; v.y = __float_as_int(g_ns[s.w]);
        g_csr2[g_rowstart[d.w] + g_pre[d.w >> 10] + r.w] = v;
    }
}

// ---------------- SpMM: warp per node, packed CSR, unroll 4, STG.128 out ------
__device__ __forceinline__ void acc_edge(uint2 u, float n, float* a1, float* a2) {
    float2 f0 = __half22float2(*reinterpret_cast<__half2*>(&u.x));
    float2 f1 = __half22float2(*reinterpret_cast<__half2*>(&u.y));
    a2[0] += f0.x; a2[1] += f0.y; a2[2] += f1.x; a2[3] += f1.y;
    a1[0] = fmaf(f0.x, n, a1[0]); a1[1] = fmaf(f0.y, n, a1[1]);
    a1[2] = fmaf(f1.x, n, a1[2]); a1[3] = fmaf(f1.y, n, a1[3]);
}

__global__ __launch_bounds__(256) void k_spmm(const uint2* __restrict__ x) {
    int w    = (blockIdx.x * 256 + threadIdx.x) >> 5;
    int lane = threadIdx.x & 31;
    if (w >= NN) return;
    int s = g_rowstart[w] + g_pre[w >> 10];
    int e = (w + 1 < NN) ? (g_rowstart[w + 1] + g_pre[(w + 1) >> 10]) : NE;
    float a1[4] = {0.f, 0.f, 0.f, 0.f};
    float a2[4] = {0.f, 0.f, 0.f, 0.f};
    int p = s;
    for (; p + 3 < e; p += 4) {
        int2  c[4];
        uint2 u[4];
        #pragma unroll
        for (int q = 0; q < 4; ++q) c[q] = g_csr2[p + q];
        #pragma unroll
        for (int q = 0; q < 4; ++q) u[q] = x[(size_t)c[q].x * 32 + lane];
        #pragma unroll
        for (int q = 0; q < 4; ++q) acc_edge(u[q], __int_as_float(c[q].y), a1, a2);
    }
    for (; p < e; ++p) {
        int2 c0 = g_csr2[p];
        uint2 u0 = x[(size_t)c0.x * 32 + lane];
        acc_edge(u0, __int_as_float(c0.y), a1, a2);
    }
    float nd = g_nd[w];
    // permuted row layout: halves [lane*8 .. lane*8+7] = [w0..w3, r0..r3]
    __half2 p0 = __floats2half2_rn(a1[0] * nd, a1[1] * nd);
    __half2 p1 = __floats2half2_rn(a1[2] * nd, a1[3] * nd);
    __half2 p2 = __floats2half2_rn(a2[0], a2[1]);
    __half2 p3 = __floats2half2_rn(a2[2], a2[3]);
    uint4 o;
    o.x = *reinterpret_cast<uint32_t*>(&p0);
    o.y = *reinterpret_cast<uint32_t*>(&p1);
    o.z = *reinterpret_cast<uint32_t*>(&p2);
    o.w = *reinterpret_cast<uint32_t*>(&p3);
    ((uint4*)g_yh)[(size_t)w * 32 + lane] = o;
}

// ---------------- GEMM: C[M,BN] = A[M,256] @ Bt[BN,256]^T + bias (fp16 mma) ---
// A rows and Bt rows share the same k-permutation -> dot products unchanged.
// Fragment loads via ldmatrix.m8n8.x4.
template <int BN, bool RELU, bool HALFOUT>
__global__ __launch_bounds__(256) void k_gemm(
    const uint32_t* __restrict__ A, const uint32_t* __restrict__ Bw,
    const float* __restrict__ bias, void* __restrict__ Cv)
{
    constexpr int BM = 128;
    constexpr int AS = 36;                 // stage row stride in words (64h + pad)
    constexpr int ASTG = BM * AS;
    constexpr int BSTG = BN * AS;
    constexpr int NT = BN / 16;            // n-tiles per warp (warp n-span BN/2)
    constexpr int NKC = 4;                 // 256 / 64 chunks

    extern __shared__ uint32_t dyn[];
    uint32_t* sA = dyn;
    uint32_t* sB = dyn + 2 * ASTG;
    const uint32_t saddrA = (uint32_t)__cvta_generic_to_shared(sA);
    const uint32_t saddrB = (uint32_t)__cvta_generic_to_shared(sB);

    const int tid  = threadIdx.x;
    const int warp = tid >> 5, lane = tid & 31;
    const int grp  = lane >> 2, tig = lane & 3;
    const int wm   = (warp >> 1) * 32;
    const int wn   = (warp & 1) * (BN / 2);
    const int blockRow = blockIdx.x * BM;

    // ldmatrix lane addressing
    const int lrowA = lane & 15;
    const int kwA   = (lane >> 4) * 4;
    const int subB  = lane & 7;
    const int nselB = (lane & 16) ? 8 : 0;
    const int kwB   = (lane & 8) ? 4 : 0;

    auto stage = [&](int kc, int buf) {
        #pragma unroll
        for (int it = 0; it < 4; ++it) {       // A chunk: 128 rows x 64 halves
            int idx = tid + it * 256;
            int r = idx >> 3, c = idx & 7;
            cp16(saddrA + (uint32_t)(buf * ASTG + r * AS + c * 4) * 4,
                 A + (size_t)(blockRow + r) * 128 + kc * 32 + c * 4);
        }
        #pragma unroll
        for (int it = 0; it < BN / 32; ++it) { // B chunk: BN rows x 64 halves
            int idx = tid + it * 256;
            int r = idx >> 3, c = idx & 7;
            cp16(saddrB + (uint32_t)(buf * BSTG + r * AS + c * 4) * 4,
                 Bw + (size_t)r * 128 + kc * 32 + c * 4);
        }
        cpcommit();
    };

    float acc[2][NT][4];
    #pragma unroll
    for (int mt = 0; mt < 2; mt++)
        #pragma unroll
        for (int nt = 0; nt < NT; nt++)
            #pragma unroll
            for (int r = 0; r < 4; r++) acc[mt][nt][r] = 0.f;

    stage(0, 0);
    #pragma unroll
    for (int kc = 0; kc < NKC; ++kc) {
        int buf = kc & 1;
        if (kc + 1 < NKC) {
            stage(kc + 1, buf ^ 1);
            cpwait<1>();
        } else {
            cpwait<0>();
        }
        __syncthreads();

        const uint32_t baseA = saddrA + (uint32_t)(buf * ASTG) * 4;
        const uint32_t baseB = saddrB + (uint32_t)(buf * BSTG) * 4;
        #pragma unroll
        for (int ks = 0; ks < 4; ++ks) {       // 4 x k16 per 64-half chunk
            uint32_t af[2][4];
            #pragma unroll
            for (int mt = 0; mt < 2; mt++) {
                uint32_t addr = baseA +
                    (uint32_t)((wm + mt * 16 + lrowA) * AS + ks * 8 + kwA) * 4;
                ldsm_x4(af[mt], addr);
            }
            uint32_t bf[NT][2];
            #pragma unroll
            for (int np = 0; np < NT / 2; np++) {
                uint32_t tmp[4];
                uint32_t addr = baseB +
                    (uint32_t)((wn + np * 16 + subB + nselB) * AS + ks * 8 + kwB) * 4;
                ldsm_x4(tmp, addr);
                bf[2 * np][0]     = tmp[0];
                bf[2 * np][1]     = tmp[1];
                bf[2 * np + 1][0] = tmp[2];
                bf[2 * np + 1][1] = tmp[3];
            }
            #pragma unroll
            for (int mt = 0; mt < 2; mt++)
                #pragma unroll
                for (int nt = 0; nt < NT; nt++)
                    mma_f16(acc[mt][nt], af[mt], bf[nt]);
        }
        __syncthreads();
    }

    // epilogue: bias (+relu), half2 or float2 stores
    #pragma unroll
    for (int mt = 0; mt < 2; ++mt) {
        int r0 = blockRow + wm + mt * 16 + grp;
        int r1 = r0 + 8;
        #pragma unroll
        for (int nt = 0; nt < NT; ++nt) {
            int col = wn + nt * 8 + 2 * tig;
            float b0v = bias[col], b1v = bias[col + 1];
            float v0 = acc[mt][nt][0] + b0v;
            float v1 = acc[mt][nt][1] + b1v;
            float v2 = acc[mt][nt][2] + b0v;
            float v3 = acc[mt][nt][3] + b1v;
            if (RELU) {
                v0 = fmaxf(v0, 0.f); v1 = fmaxf(v1, 0.f);
                v2 = fmaxf(v2, 0.f); v3 = fmaxf(v3, 0.f);
            }
            if (HALFOUT) {
                __half* C = (__half*)Cv;
                if (r0 < NN)
                    *reinterpret_cast<__half2*>(&C[(size_t)r0 * BN + col]) =
                        __floats2half2_rn(v0, v1);
                if (r1 < NN)
                    *reinterpret_cast<__half2*>(&C[(size_t)r1 * BN + col]) =
                        __floats2half2_rn(v2, v3);
            } else {
                float* C = (float*)Cv;
                if (r0 < NN)
                    *reinterpret_cast<float2*>(&C[(size_t)r0 * BN + col]) = make_float2(v0, v1);
                if (r1 < NN)
                    *reinterpret_cast<float2*>(&C[(size_t)r1 * BN + col]) = make_float2(v2, v3);
            }
        }
    }
}

// ---------------- launcher ----------------------------------------------------
extern "C" void kernel_launch(void* const* d_in, const int* in_sizes, int n_in,
                              void* d_out, int out_size) {
    const float* raw_x = (const float*)d_in[0];
    const int*   src   = (const int*)d_in[1];
    const int*   dst   = (const int*)d_in[2];
    const float* w0    = (const float*)d_in[3];
    const float* b0    = (const float*)d_in[4];
    const float* w1    = (const float*)d_in[5];
    const float* b1    = (const float*)d_in[6];
    const float* w2    = (const float*)d_in[7];
    const float* b2    = (const float*)d_in[8];
    const float* rw0   = (const float*)d_in[9];
    const float* rw1   = (const float*)d_in[10];
    const float* rw2   = (const float*)d_in[11];
    float* out = (float*)d_out;

    void *py = nullptr, *pf0 = nullptr, *pf1 = nullptr;
    void *pw0 = nullptr, *pw1 = nullptr, *pw2 = nullptr;
    cudaGetSymbolAddress(&py, g_yh);
    cudaGetSymbolAddress(&pf0, g_f0);
    cudaGetSymbolAddress(&pf1, g_f1);
    cudaGetSymbolAddress(&pw0, g_wt0);
    cudaGetSymbolAddress(&pw1, g_wt1);
    cudaGetSymbolAddress(&pw2, g_wt2);

    constexpr int SMEM128 = 2 * (128 * 36 + 128 * 36) * 4;  // 73728
    constexpr int SMEM64  = 2 * (128 * 36 + 64 * 36) * 4;   // 55296
    cudaFuncSetAttribute(k_gemm<128, true, true>,
                         cudaFuncAttributeMaxDynamicSharedMemorySize, SMEM128);
    cudaFuncSetAttribute(k_gemm<64, false, false>,
                         cudaFuncAttributeMaxDynamicSharedMemorySize, SMEM64);

    const int TB = 256;
    k_prep<<<(3331920 + TB - 1) / TB, TB>>>((const float4*)raw_x,
                                            w0, rw0, w1, rw1, w2, rw2);
    k_deg<<<(NE / 4 + TB - 1) / TB, TB>>>((const int4*)src, (const int4*)dst);
    k_scan1<<<SCAN_NB, 1024>>>();
    k_csr<<<(NE / 4 + TB - 1) / TB, TB>>>((const int4*)src, (const int4*)dst);

    const int SPMM_BLOCKS = (NN * 32 + TB - 1) / TB;  // one warp per node
    const int GEMM_BLOCKS = NN_PAD / 128;             // 782

    // layer 1: spmm(g_f0=x) -> g_yh ; gemm -> g_f1 (h1, fp16)
    k_spmm<<<SPMM_BLOCKS, TB>>>((const uint2*)pf0);
    k_gemm<128, true, true><<<GEMM_BLOCKS, TB, SMEM128>>>(
        (const uint32_t*)py, (const uint32_t*)pw0, b0, pf1);
    // layer 2: spmm(g_f1) -> g_yh ; gemm -> g_f0 (h2, fp16)
    k_spmm<<<SPMM_BLOCKS, TB>>>((const uint2*)pf1);
    k_gemm<128, true, true><<<GEMM_BLOCKS, TB, SMEM128>>>(
        (const uint32_t*)py, (const uint32_t*)pw1, b1, pf0);
    // layer 3: spmm(g_f0) -> g_yh ; gemm -> d_out (fp32)
    k_spmm<<<SPMM_BLOCKS, TB>>>((const uint2*)pf0);
    k_gemm<64, false, false><<<GEMM_BLOCKS, TB, SMEM64>>>(
        (const uint32_t*)py, (const uint32_t*)pw2, b2, out);
}